// round 17
// baseline (speedup 1.0000x reference)
#include <cuda_runtime.h>
#include <cuda_bf16.h>
#include <cuda_fp16.h>
#include <cstdint>
#include <math.h>

// Problem constants
#define Bq 8
#define Nq 1025
#define Cq 3200
#define Hq 25
#define Dq 128
#define Mq (Bq * Nq)        // 8200
#define QKV_N (3 * Cq)      // 9600
#define EPSq 1e-6f

// Scratch (__device__ globals per alloc-free rule)
__device__ __half g_qkv16[(size_t)Mq * 2 * Cq];     // q,k fp16 (GEMM output)
__device__ __half g_as[(size_t)Mq * Cq];            // fp16 A (x, then attn out)
__device__ __half g_wq[(size_t)QKV_N * Cq];         // qkv_w^T fp16
__device__ __half g_wp[(size_t)Cq * Cq];            // proj_w^T fp16
__device__ __half g_q[(size_t)Bq * Hq * Nq * 128];  // q: fp16, normed+scaled
__device__ __half g_k[(size_t)Bq * Hq * Nq * 128];  // k: fp16, normed
__device__ __half g_v[(size_t)Bq * Hq * Nq * 128];  // v: fp16 (GEMM-direct)

// ===========================================================================
// helpers
// ===========================================================================
__device__ __forceinline__ uint32_t smem_u32(const void* p) {
    uint32_t a;
    asm("{ .reg .u64 t; cvta.to.shared.u64 t, %1; cvt.u32.u64 %0, t; }"
        : "=r"(a) : "l"(p));
    return a;
}
__device__ __forceinline__ uint32_t swz128(uint32_t off) {
    return off ^ ((off >> 3) & 0x70);
}
__device__ __forceinline__ void cp16(uint32_t s, const void* g) {
    asm volatile("cp.async.cg.shared.global [%0], [%1], 16;"
                 :: "r"(s), "l"(g) : "memory");
}
__device__ __forceinline__ void cp16z(uint32_t s, const void* g, int sz) {
    asm volatile("cp.async.cg.shared.global [%0], [%1], 16, %2;"
                 :: "r"(s), "l"(g), "r"(sz) : "memory");
}
#define CP_COMMIT() asm volatile("cp.async.commit_group;" ::: "memory")

#define LDSM_X4(r, addr)                                                       \
    asm volatile("ldmatrix.sync.aligned.m8n8.x4.shared.b16 {%0,%1,%2,%3}, [%4];" \
        : "=r"((r)[0]), "=r"((r)[1]), "=r"((r)[2]), "=r"((r)[3]) : "r"(addr))

#define LDSM_X4_T(r, addr)                                                     \
    asm volatile("ldmatrix.sync.aligned.m8n8.x4.trans.shared.b16 {%0,%1,%2,%3}, [%4];" \
        : "=r"((r)[0]), "=r"((r)[1]), "=r"((r)[2]), "=r"((r)[3]) : "r"(addr))

#define MMA16816_F16(d, a, b)                                                  \
    asm volatile("mma.sync.aligned.m16n8k16.row.col.f32.f16.f16.f32 "          \
        "{%0,%1,%2,%3}, {%4,%5,%6,%7}, {%8,%9}, {%0,%1,%2,%3};"                \
        : "+f"((d)[0]), "+f"((d)[1]), "+f"((d)[2]), "+f"((d)[3])               \
        : "r"((a)[0]), "r"((a)[1]), "r"((a)[2]), "r"((a)[3]),                  \
          "r"((b)[0]), "r"((b)[1]))

__device__ __forceinline__ uint32_t pack_h(float x, float y) {
    __half2 h2; h2.x = __float2half_rn(x); h2.y = __float2half_rn(y);
    return *(uint32_t*)&h2;
}

// ===========================================================================
// Convert kernels
// ===========================================================================
__global__ __launch_bounds__(256) void conv_a_kernel(
    const float* __restrict__ in, __half* __restrict__ out, int M)
{
    size_t idx = ((size_t)blockIdx.x * 256 + threadIdx.x) * 4;
    if (idx >= (size_t)M * Cq) return;
    float4 v = *(const float4*)(in + idx);
    *(uint32_t*)(out + idx)     = pack_h(v.x, v.y);
    *(uint32_t*)(out + idx + 2) = pack_h(v.z, v.w);
}

__global__ __launch_bounds__(256) void split_wt_kernel(
    const float* __restrict__ W, __half* __restrict__ out, int Nw)
{
    __shared__ float tile[32][33];
    int n0 = blockIdx.x * 32, k0 = blockIdx.y * 32;
    int tx = threadIdx.x, ty = threadIdx.y;
    #pragma unroll
    for (int i = ty; i < 32; i += 8)
        tile[i][tx] = W[(size_t)(k0 + i) * Nw + n0 + tx];
    __syncthreads();
    #pragma unroll
    for (int i = ty; i < 32; i += 8) {
        int n = n0 + i, k = k0 + tx;
        out[(size_t)n * Cq + k] = __float2half_rn(tile[tx][i]);
    }
}

// ===========================================================================
// Plain fp16 mma.sync GEMM (proven mainloop).
// mode 0: fp32 C (+bias)                     [proj]
// mode 1: fp16 out: q,k -> qkv16; v -> g_v head-contiguous   [qkv]
// Tail m-tile: warps whose 64-row slice is fully out of range skip compute.
// ===========================================================================
#define GBM 128
#define GBN 128
#define GBK 64
#define GNIT (Cq / GBK)            // 50
#define ABYTES (GBM * GBK * 2)
#define BBYTES (GBN * GBK * 2)
#define BUFB (ABYTES + BBYTES)
#define GSTAGES 3
#define GSMEM_TOTAL (GSTAGES * BUFB)
#define G_GM 8

__global__ __launch_bounds__(256, 2) void gemm_mma(
    const __half* __restrict__ A,
    const __half* __restrict__ Bt,
    const float* __restrict__ bias,
    void* __restrict__ Cout,
    __half* __restrict__ vout,
    int M, int Nt, int mt, int nt, int mode)
{
    extern __shared__ char smem[];
    const uint32_t sbase = smem_u32(smem);
    const int tid = threadIdx.x;
    const int wid = tid >> 5, lane = tid & 31;
    const int wm = wid >> 2, wn = wid & 3;

    int bid = blockIdx.x;
    int per_group = G_GM * nt;
    int gid = bid / per_group;
    int first_m = gid * G_GM;
    int gsz = min(G_GM, mt - first_m);
    int rem = bid % per_group;
    const int m0 = (first_m + rem % gsz) * GBM;
    const int n0 = (rem / gsz) * GBN;

    const bool wactive = (m0 + wm * 64) < M;   // dead-warp guard (tail m-tile)

    float acc[4][4][4];
    #pragma unroll
    for (int i = 0; i < 4; i++)
        #pragma unroll
        for (int j = 0; j < 4; j++)
            #pragma unroll
            for (int r = 0; r < 4; r++) acc[i][j][r] = 0.f;

    auto load_tile = [&](int it, int buf) {
        const int k0 = it * GBK;
        const uint32_t sA = sbase + buf * BUFB;
        const uint32_t sB = sA + ABYTES;
        #pragma unroll
        for (int p = 0; p < 4; p++) {
            int id = p * 256 + tid;
            int row = id >> 3, ch = id & 7;
            uint32_t so = swz128((uint32_t)(row * 128 + ch * 16));
            int m = min(m0 + row, M - 1);
            cp16(sA + so, A  + (size_t)m * Cq + k0 + ch * 8);
            cp16(sB + so, Bt + (size_t)(n0 + row) * Cq + k0 + ch * 8);
        }
        CP_COMMIT();
    };

    auto compute = [&](int buf) {
        const uint32_t sA = sbase + buf * BUFB + (uint32_t)(wm * 64 * 128);
        const uint32_t sB = sbase + buf * BUFB + ABYTES + (uint32_t)(wn * 32 * 128);
        #pragma unroll
        for (int kk = 0; kk < 4; kk++) {
            uint32_t afr[4][4];
            #pragma unroll
            for (int mi = 0; mi < 4; mi++) {
                int row = mi * 16 + (lane & 15);
                int cb = kk * 32 + ((lane >> 4) << 4);
                LDSM_X4(afr[mi], sA + swz128((uint32_t)(row * 128 + cb)));
            }
            uint32_t bfr[4][2];
            #pragma unroll
            for (int bj = 0; bj < 2; bj++) {
                int row = bj * 16 + ((lane >> 4) << 3) + (lane & 7);
                int cb = kk * 32 + (((lane >> 3) & 1) << 4);
                uint32_t r[4];
                LDSM_X4(r, sB + swz128((uint32_t)(row * 128 + cb)));
                bfr[2 * bj][0] = r[0];     bfr[2 * bj][1] = r[1];
                bfr[2 * bj + 1][0] = r[2]; bfr[2 * bj + 1][1] = r[3];
            }
            #pragma unroll
            for (int mi = 0; mi < 4; mi++)
                #pragma unroll
                for (int nj = 0; nj < 4; nj++)
                    MMA16816_F16(acc[mi][nj], afr[mi], bfr[nj]);
        }
    };

    load_tile(0, 0);
    load_tile(1, 1);
    for (int it = 0; it < GNIT; it++) {
        if (it + 1 < GNIT)
            asm volatile("cp.async.wait_group 1;" ::: "memory");
        else
            asm volatile("cp.async.wait_group 0;" ::: "memory");
        __syncthreads();
        if (it + 2 < GNIT) load_tile(it + 2, (it + 2) % GSTAGES);
        if (wactive) compute(it % GSTAGES);
    }

    if (!wactive) return;

    const int mbase = m0 + wm * 64;
    const int nbase = n0 + wn * 32;
    #pragma unroll
    for (int mi = 0; mi < 4; mi++) {
        #pragma unroll
        for (int nj = 0; nj < 4; nj++) {
            int r0 = mbase + mi * 16 + (lane >> 2);
            int c = nbase + nj * 8 + 2 * (lane & 3);
            float bx = bias[c], by = bias[c + 1];
            float v00 = acc[mi][nj][0] + bx, v01 = acc[mi][nj][1] + by;
            float v10 = acc[mi][nj][2] + bx, v11 = acc[mi][nj][3] + by;
            if (mode == 0) {
                float* C = (float*)Cout;
                if (r0 < M)
                    *(float2*)(C + (size_t)r0 * Nt + c) = make_float2(v00, v01);
                if (r0 + 8 < M)
                    *(float2*)(C + (size_t)(r0 + 8) * Nt + c) = make_float2(v10, v11);
            } else {
                if (c < 2 * Cq) {
                    __half* C = (__half*)Cout;
                    if (r0 < M)
                        *(uint32_t*)(C + (size_t)r0 * 2 * Cq + c) = pack_h(v00, v01);
                    if (r0 + 8 < M)
                        *(uint32_t*)(C + (size_t)(r0 + 8) * 2 * Cq + c) = pack_h(v10, v11);
                } else {
                    int cc = c - 2 * Cq;
                    int h = cc >> 7, d = cc & 127;
                    if (r0 < M) {
                        int b = r0 / Nq, nn = r0 % Nq;
                        *(uint32_t*)(vout + ((size_t)(b * Hq + h) * Nq + nn) * 128 + d)
                            = pack_h(v00, v01);
                    }
                    if (r0 + 8 < M) {
                        int b = (r0 + 8) / Nq, nn = (r0 + 8) % Nq;
                        *(uint32_t*)(vout + ((size_t)(b * Hq + h) * Nq + nn) * 128 + d)
                            = pack_h(v10, v11);
                    }
                }
            }
        }
    }
}

// ===========================================================================
// Fused rmsnorm + head-contiguous relayout, fp16 in/out (proven).
// ===========================================================================
__global__ __launch_bounds__(256) void fuse_nc(
    const __half* __restrict__ qkv16,
    const float* __restrict__ qw, const float* __restrict__ kw,
    __half* __restrict__ gq, __half* __restrict__ gk)
{
    const int row = blockIdx.x;
    const int which = blockIdx.y;       // 0 q, 1 k
    const int b = row / Nq, n = row % Nq;
    const __half* p = qkv16 + (size_t)row * 2 * Cq + which * Cq;
    const int tid = threadIdx.x;

    float ss = 0.f;
    for (int c = tid * 8; c < Cq; c += 2048) {
        uint4 u = *(const uint4*)(p + c);
        const __half2* h2 = (const __half2*)&u;
        #pragma unroll
        for (int j = 0; j < 4; j++) {
            float2 f = __half22float2(h2[j]);
            ss += f.x * f.x + f.y * f.y;
        }
    }
    #pragma unroll
    for (int o = 16; o; o >>= 1) ss += __shfl_xor_sync(0xffffffffu, ss, o);
    __shared__ float red[8];
    if ((tid & 31) == 0) red[tid >> 5] = ss;
    __syncthreads();
    if (tid < 8) {
        float v = red[tid];
        #pragma unroll
        for (int o = 4; o; o >>= 1) v += __shfl_xor_sync(0xffu, v, o);
        if (tid == 0) red[0] = v;
    }
    __syncthreads();
    const float sc = which ? 1.f : 0.08838834764831845f;
    const float inv = rsqrtf(red[0] * (1.f / Cq) + EPSq) * sc;
    const float* w = which ? kw : qw;
    __half* g = which ? gk : gq;

    for (int c = tid * 8; c < Cq; c += 2048) {
        uint4 u = *(const uint4*)(p + c);
        const __half2* h2 = (const __half2*)&u;
        float4 w0 = *(const float4*)(w + c);
        float4 w1 = *(const float4*)(w + c + 4);
        int h = c >> 7, d = c & 127;
        __half* orow = g + ((size_t)(b * Hq + h) * Nq + n) * 128;
        float2 f0 = __half22float2(h2[0]);
        float2 f1 = __half22float2(h2[1]);
        float2 f2 = __half22float2(h2[2]);
        float2 f3 = __half22float2(h2[3]);
        uint4 o;
        o.x = pack_h(f0.x * inv * w0.x, f0.y * inv * w0.y);
        o.y = pack_h(f1.x * inv * w0.z, f1.y * inv * w0.w);
        o.z = pack_h(f2.x * inv * w1.x, f2.y * inv * w1.y);
        o.w = pack_h(f3.x * inv * w1.z, f3.y * inv * w1.w);
        *(uint4*)(orow + d) = o;
    }
}

// ===========================================================================
// FA2-style flash attention, single-pass fp16.
// New: per-warp activity guard (qt=8 CTAs have 1 valid q-row) and reduced
// tail key-tile (kt=16 has 1 valid key) — both remove only discarded/zero
// work, bit-identical results.
// ===========================================================================
#define ZK_B 272
#define ZKBUF (64 * ZK_B)
#define ZA_Q 0
#define ZA_K (128 * ZK_B)
#define ZA_V (ZA_K + 2 * ZKBUF)
#define ZSMEM (ZA_V + 2 * ZKBUF)

__global__ __launch_bounds__(256, 2) void fa2(
    const __half* __restrict__ gq, const __half* __restrict__ gk,
    const __half* __restrict__ gv, __half* __restrict__ outAs)
{
    extern __shared__ char sm[];
    const uint32_t sq = smem_u32(sm + ZA_Q);
    const uint32_t sk = smem_u32(sm + ZA_K);
    const uint32_t sv = smem_u32(sm + ZA_V);

    const int qt = blockIdx.x, h = blockIdx.y, b = blockIdx.z;
    const int tid = threadIdx.x, w = tid >> 5, lane = tid & 31;
    const int q0 = qt * 128;
    const bool wactive = (q0 + w * 16) < Nq;   // warp has >=1 valid q-row

    const __half* qb = gq + (size_t)(b * Hq + h) * Nq * 128;
    const __half* kb = gk + (size_t)(b * Hq + h) * Nq * 128;
    const __half* vb = gv + (size_t)(b * Hq + h) * Nq * 128;

    for (int i = tid; i < 128 * 16; i += 256) {
        int r = i >> 4, ch = i & 15;
        int n = q0 + r;
        int nc = min(n, Nq - 1);
        cp16z(sq + (uint32_t)(r * ZK_B + ch * 16),
              qb + (size_t)nc * 128 + ch * 8, (n < Nq) ? 16 : 0);
    }
    CP_COMMIT();

    auto fillKV = [&](int kt, int buf) {
        const int k0 = kt * 64;
        const uint32_t dk = sk + buf * ZKBUF;
        const uint32_t dv = sv + buf * ZKBUF;
        for (int i = tid; i < 64 * 16; i += 256) {
            int r = i >> 4, ch = i & 15;
            int n = k0 + r;
            int nc = min(n, Nq - 1);
            int sz = (n < Nq) ? 16 : 0;
            cp16z(dk + (uint32_t)(r * ZK_B + ch * 16), kb + (size_t)nc * 128 + ch * 8, sz);
            cp16z(dv + (uint32_t)(r * ZK_B + ch * 16), vb + (size_t)nc * 128 + ch * 8, sz);
        }
        CP_COMMIT();
    };
    fillKV(0, 0);

    float m0 = -1e30f, m1 = -1e30f, l0 = 0.f, l1 = 0.f;
    float acc_o[16][4];
    #pragma unroll
    for (int g = 0; g < 16; g++)
        #pragma unroll
        for (int r = 0; r < 4; r++) acc_o[g][r] = 0.f;

    const int arow = w * 16 + (lane & 15);
    const uint32_t a_cb = (uint32_t)((lane >> 4) << 4);
    const int krow_b = ((lane >> 4) << 3) + (lane & 7);
    const uint32_t b_cb = (uint32_t)(((lane >> 3) & 1) << 4);
    const int vrow_b = (lane & 7) + (((lane >> 3) & 1) << 3);
    const uint32_t v_cb = (uint32_t)((lane >> 4) << 4);

    for (int kt = 0; kt < 17; kt++) {
        const int buf = kt & 1;
        asm volatile("cp.async.wait_group 0;" ::: "memory");
        __syncthreads();
        if (kt < 16) fillKV(kt + 1, buf ^ 1);

        if (!wactive) continue;

        const uint32_t skb = sk + buf * ZKBUF;
        const uint32_t svb = sv + buf * ZKBUF;
        const bool tail = (kt == 16);     // only key 1024 valid
        const int bjmax = tail ? 1 : 4;
        const int njmax = tail ? 2 : 8;
        const int kcmax = tail ? 1 : 4;

        // ---- S = Qh Kh^T ----
        float accs[8][4];
        #pragma unroll
        for (int nj = 0; nj < 8; nj++)
            #pragma unroll
            for (int r = 0; r < 4; r++) accs[nj][r] = 0.f;

        #pragma unroll
        for (int ks = 0; ks < 8; ks++) {
            uint32_t afr[4];
            LDSM_X4(afr, sq + (uint32_t)(arow * ZK_B + ks * 32) + a_cb);
            for (int bj = 0; bj < bjmax; bj++) {
                uint32_t r[4];
                LDSM_X4(r, skb + (uint32_t)((bj * 16 + krow_b) * ZK_B + ks * 32) + b_cb);
                uint32_t b0[2] = {r[0], r[1]};
                uint32_t b1[2] = {r[2], r[3]};
                MMA16816_F16(accs[2 * bj],     afr, b0);
                MMA16816_F16(accs[2 * bj + 1], afr, b1);
            }
        }

        if (tail) {
            #pragma unroll
            for (int nj = 0; nj < 2; nj++)
                #pragma unroll
                for (int j = 0; j < 4; j++) {
                    int col = 1024 + nj * 8 + 2 * (lane & 3) + (j & 1);
                    if (col >= Nq) accs[nj][j] = -1e30f;
                }
        }

        // ---- register softmax (over valid fragments only) ----
        float mx0 = -1e30f, mx1 = -1e30f;
        for (int nj = 0; nj < njmax; nj++) {
            mx0 = fmaxf(mx0, fmaxf(accs[nj][0], accs[nj][1]));
            mx1 = fmaxf(mx1, fmaxf(accs[nj][2], accs[nj][3]));
        }
        mx0 = fmaxf(mx0, __shfl_xor_sync(0xffffffffu, mx0, 1));
        mx0 = fmaxf(mx0, __shfl_xor_sync(0xffffffffu, mx0, 2));
        mx1 = fmaxf(mx1, __shfl_xor_sync(0xffffffffu, mx1, 1));
        mx1 = fmaxf(mx1, __shfl_xor_sync(0xffffffffu, mx1, 2));

        const float mn0 = fmaxf(m0, mx0), mn1 = fmaxf(m1, mx1);
        const float cr0 = __expf(m0 - mn0), cr1 = __expf(m1 - mn1);

        float s0 = 0.f, s1 = 0.f;
        uint32_t ph[8][2];
        for (int nj = 0; nj < njmax; nj++) {
            float p0 = __expf(accs[nj][0] - mn0);
            float p1 = __expf(accs[nj][1] - mn0);
            float p2 = __expf(accs[nj][2] - mn1);
            float p3 = __expf(accs[nj][3] - mn1);
            s0 += p0 + p1; s1 += p2 + p3;
            ph[nj][0] = pack_h(p0, p1);
            ph[nj][1] = pack_h(p2, p3);
        }
        s0 += __shfl_xor_sync(0xffffffffu, s0, 1);
        s0 += __shfl_xor_sync(0xffffffffu, s0, 2);
        s1 += __shfl_xor_sync(0xffffffffu, s1, 1);
        s1 += __shfl_xor_sync(0xffffffffu, s1, 2);
        l0 = l0 * cr0 + s0; l1 = l1 * cr1 + s1;
        m0 = mn0; m1 = mn1;

        #pragma unroll
        for (int g = 0; g < 16; g++) {
            acc_o[g][0] *= cr0; acc_o[g][1] *= cr0;
            acc_o[g][2] *= cr1; acc_o[g][3] *= cr1;
        }

        // ---- O += Ph Vh ----
        for (int kc = 0; kc < kcmax; kc++) {
            uint32_t aPh[4] = {ph[2 * kc][0], ph[2 * kc][1], ph[2 * kc + 1][0], ph[2 * kc + 1][1]};
            #pragma unroll
            for (int g2 = 0; g2 < 8; g2++) {
                uint32_t r[4];
                LDSM_X4_T(r, svb + (uint32_t)((kc * 16 + vrow_b) * ZK_B + g2 * 32) + v_cb);
                uint32_t b0[2] = {r[0], r[1]};
                uint32_t b1[2] = {r[2], r[3]};
                MMA16816_F16(acc_o[2 * g2],     aPh, b0);
                MMA16816_F16(acc_o[2 * g2 + 1], aPh, b1);
            }
        }
    }

    // ---- epilogue: normalize, write fp16 (stride Cq) ----
    if (wactive) {
        const float invl0 = 1.f / l0, invl1 = 1.f / l1;
        const int n0v = q0 + w * 16 + (lane >> 2);
        const int n1v = n0v + 8;
        #pragma unroll
        for (int g = 0; g < 16; g++) {
            int c = h * Dq + g * 8 + 2 * (lane & 3);
            if (n0v < Nq) {
                __half* row = outAs + (size_t)(b * Nq + n0v) * Cq;
                *(uint32_t*)(row + c) = pack_h(acc_o[g][0] * invl0, acc_o[g][1] * invl0);
            }
            if (n1v < Nq) {
                __half* row = outAs + (size_t)(b * Nq + n1v) * Cq;
                *(uint32_t*)(row + c) = pack_h(acc_o[g][2] * invl1, acc_o[g][3] * invl1);
            }
        }
    }
}

// ===========================================================================
extern "C" void kernel_launch(void* const* d_in, const int* in_sizes, int n_in,
                              void* d_out, int out_size)
{
    const float* x        = (const float*)d_in[0];
    const float* qkv_w    = (const float*)d_in[1];
    const float* qkv_b    = (const float*)d_in[2];
    const float* q_norm_w = (const float*)d_in[3];
    const float* k_norm_w = (const float*)d_in[4];
    const float* proj_w   = (const float*)d_in[5];
    const float* proj_b   = (const float*)d_in[6];
    float* out = (float*)d_out;

    __half *qkvp = nullptr, *asp = nullptr, *wqp = nullptr, *wpp = nullptr;
    __half *qp = nullptr, *kp = nullptr, *vp = nullptr;
    cudaGetSymbolAddress((void**)&qkvp, g_qkv16);
    cudaGetSymbolAddress((void**)&asp, g_as);
    cudaGetSymbolAddress((void**)&wqp, g_wq);
    cudaGetSymbolAddress((void**)&wpp, g_wp);
    cudaGetSymbolAddress((void**)&qp, g_q);
    cudaGetSymbolAddress((void**)&kp, g_k);
    cudaGetSymbolAddress((void**)&vp, g_v);

    cudaFuncSetAttribute(gemm_mma,
                         cudaFuncAttributeMaxDynamicSharedMemorySize, GSMEM_TOTAL);
    cudaFuncSetAttribute(fa2,
                         cudaFuncAttributeMaxDynamicSharedMemorySize, ZSMEM);

    const int mt = (Mq + GBM - 1) / GBM;        // 65
    const int nt_qkv = QKV_N / GBN;             // 75
    const int nt_prj = Cq / GBN;                // 25

    // 1) convert x to fp16; round weights to fp16 (transposed)
    {
        size_t e4 = (size_t)Mq * Cq / 4;
        conv_a_kernel<<<(unsigned)((e4 + 255) / 256), 256>>>(x, asp, Mq);
    }
    split_wt_kernel<<<dim3(QKV_N / 32, Cq / 32), dim3(32, 8)>>>(qkv_w, wqp, QKV_N);
    split_wt_kernel<<<dim3(Cq / 32, Cq / 32), dim3(32, 8)>>>(proj_w, wpp, Cq);

    // 2) qkv GEMM: q,k -> g_qkv16 fp16; v -> g_v (head layout) directly
    gemm_mma<<<mt * nt_qkv, 256, GSMEM_TOTAL>>>(
        asp, wqp, qkv_b, qkvp, vp, Mq, QKV_N, mt, nt_qkv, 1);

    // 3) fused rmsnorm + relayout -> g_q / g_k
    fuse_nc<<<dim3(Mq, 2), 256>>>(qkvp, q_norm_w, k_norm_w, qp, kp);

    // 4) FA2 attention -> g_as (fp16)
    fa2<<<dim3(9, Hq, Bq), 256, ZSMEM>>>(qp, kp, vp, asp);

    // 5) out = att @ proj_w + b (fp32 out)
    gemm_mma<<<mt * nt_prj, 256, GSMEM_TOTAL>>>(
        asp, wpp, proj_b, out, nullptr, Mq, Cq, mt, nt_prj, 0);
}